// round 2
// baseline (speedup 1.0000x reference)
#include <cuda_runtime.h>

#define CH 192
#define NB 8
#define HW 16384
#define KSPLIT 8
#define KCHUNK (HW / KSPLIT)
#define EPSN 1e-12f

// ---------------- scratch (static device memory; no allocations) ----------------
__device__ float g_Wq[CH*CH], g_Wk[CH*CH], g_Wv[CH*CH], g_Wp2[CH*CH], g_bp2[CH];
__device__ float g_Spart[NB*KSPLIT*CH*CH];
__device__ float g_S[NB*CH*CH], g_T1[NB*CH*CH], g_T2[NB*CH*CH];
__device__ float g_G[NB*CH*CH], g_attn[NB*CH*CH], g_A1[NB*CH*CH], g_A2[NB*CH*CH];
__device__ float g_nk2[NB*CH], g_nq2[NB*CH];

// ---------------- generic tiny 192x192 GEMM: C[b] = A (x) B ----------------
// aBatched/bBatched: operand has per-batch stride CH*CH. transB: C = A * B^T.
__global__ void gemm192(const float* __restrict__ A, const float* __restrict__ Bm,
                        float* __restrict__ Cm, int aBatched, int bBatched, int transB) {
    __shared__ float As[16][17], Bs[16][17];
    int b = blockIdx.y;
    const float* Ab = A  + (aBatched ? b*CH*CH : 0);
    const float* Bb = Bm + (bBatched ? b*CH*CH : 0);
    float* Cb = Cm + b*CH*CH;
    int tile = blockIdx.x;           // 0..143 (12x12 tiles of 16)
    int i0 = (tile / 12) * 16;
    int j0 = (tile % 12) * 16;
    int tx = threadIdx.x, ty = threadIdx.y;
    float acc = 0.f;
    if (transB) {
        for (int kk = 0; kk < CH; kk += 16) {
            As[ty][tx] = Ab[(i0+ty)*CH + kk + tx];
            Bs[ty][tx] = Bb[(j0+ty)*CH + kk + tx];
            __syncthreads();
            #pragma unroll
            for (int k = 0; k < 16; ++k) acc += As[ty][k] * Bs[tx][k];
            __syncthreads();
        }
    } else {
        for (int kk = 0; kk < CH; kk += 16) {
            As[ty][tx] = Ab[(i0+ty)*CH + kk + tx];
            Bs[ty][tx] = Bb[(kk+ty)*CH + j0 + tx];
            __syncthreads();
            #pragma unroll
            for (int k = 0; k < 16; ++k) acc += As[ty][k] * Bs[k][tx];
            __syncthreads();
        }
    }
    Cb[(i0+ty)*CH + j0 + tx] = acc;
}

// bp2[f] = sum_o w_out[f][o] * b_proj[o]
__global__ void bias_combine(const float* __restrict__ w_out, const float* __restrict__ b_proj) {
    int f = threadIdx.x;
    if (f < CH) {
        float s = 0.f;
        for (int o = 0; o < CH; ++o) s += w_out[f*CH+o] * b_proj[o];
        g_bp2[f] = s;
    }
}

// ---------------- S = X X^T (per batch), split-K partials (deterministic) ----------------
__global__ __launch_bounds__(256) void xxt_partial(const float* __restrict__ xin) {
    __shared__ float As[16][68], Bs[16][68];
    int bz = blockIdx.z;
    int b = bz / KSPLIT, p = bz % KSPLIT;
    const float* Xb = xin + (size_t)b * CH * HW;
    int i0 = blockIdx.x * 64, j0 = blockIdx.y * 64;
    int tid = threadIdx.x;
    int tx = tid & 15, ty = tid >> 4;
    int lr = tid >> 2;             // 0..63
    int lk = (tid & 3) * 4;        // 0,4,8,12
    int kstart = p * KCHUNK;
    float acc[4][4] = {};
    for (int kt = 0; kt < KCHUNK; kt += 16) {
        int kb = kstart + kt;
        float4 av = *(const float4*)&Xb[(size_t)(i0+lr)*HW + kb + lk];
        float4 bv = *(const float4*)&Xb[(size_t)(j0+lr)*HW + kb + lk];
        __syncthreads();
        As[lk+0][lr]=av.x; As[lk+1][lr]=av.y; As[lk+2][lr]=av.z; As[lk+3][lr]=av.w;
        Bs[lk+0][lr]=bv.x; Bs[lk+1][lr]=bv.y; Bs[lk+2][lr]=bv.z; Bs[lk+3][lr]=bv.w;
        __syncthreads();
        #pragma unroll
        for (int k = 0; k < 16; ++k) {
            float4 a4 = *(const float4*)&As[k][ty*4];
            float4 b4 = *(const float4*)&Bs[k][tx*4];
            float aa[4] = {a4.x,a4.y,a4.z,a4.w};
            float bb[4] = {b4.x,b4.y,b4.z,b4.w};
            #pragma unroll
            for (int ii = 0; ii < 4; ++ii)
                #pragma unroll
                for (int jj = 0; jj < 4; ++jj)
                    acc[ii][jj] += aa[ii]*bb[jj];
        }
    }
    float* outp = g_Spart + (size_t)(b*KSPLIT + p)*CH*CH;
    #pragma unroll
    for (int ii = 0; ii < 4; ++ii) {
        float4 o = {acc[ii][0], acc[ii][1], acc[ii][2], acc[ii][3]};
        *(float4*)&outp[(i0+ty*4+ii)*CH + j0 + tx*4] = o;
    }
}

__global__ void s_reduce() {
    int idx = blockIdx.x*256 + threadIdx.x;   // over NB*CH*CH = 294912
    if (idx < NB*CH*CH) {
        int b = idx / (CH*CH), e = idx % (CH*CH);
        float s = 0.f;
        #pragma unroll
        for (int p = 0; p < KSPLIT; ++p)
            s += g_Spart[(size_t)(b*KSPLIT+p)*CH*CH + e];
        g_S[idx] = s;
    }
}

// nq2[b][j] = diag(Wq' T1)_j ; nk2[b][i] = diag(Wk' T2)_i
__global__ void diag_norms() {
    int b = blockIdx.x, which = blockIdx.y;
    int j = threadIdx.x;
    if (j >= CH) return;
    const float* W = which ? g_Wk : g_Wq;
    const float* T = (which ? g_T2 : g_T1) + (size_t)b*CH*CH;
    float s = 0.f;
    for (int m = 0; m < CH; ++m) s += W[j*CH+m] * T[m*CH+j];
    (which ? g_nk2 : g_nq2)[b*CH+j] = s;
}

// attn[i][j] = softmax_j( G[i][j] / (max(||k_i||,eps)*max(||q_j||,eps)) )
__global__ void softmax_rows() {
    int b = blockIdx.y, i = blockIdx.x;
    int j = threadIdx.x;                  // 192 threads, 6 full warps
    const float* Grow = g_G + ((size_t)b*CH + i)*CH;
    float dk = fmaxf(sqrtf(g_nk2[b*CH+i]), EPSN);
    float dq = fmaxf(sqrtf(g_nq2[b*CH+j]), EPSN);
    float L = Grow[j] / (dk*dq);
    __shared__ float redm[6], reds[6];
    float m = L;
    #pragma unroll
    for (int o = 16; o > 0; o >>= 1) m = fmaxf(m, __shfl_xor_sync(0xffffffffu, m, o));
    if ((j & 31) == 0) redm[j>>5] = m;
    __syncthreads();
    float mx = fmaxf(fmaxf(fmaxf(redm[0],redm[1]),fmaxf(redm[2],redm[3])),fmaxf(redm[4],redm[5]));
    float e = expf(L - mx);
    float s = e;
    #pragma unroll
    for (int o = 16; o > 0; o >>= 1) s += __shfl_xor_sync(0xffffffffu, s, o);
    if ((j & 31) == 0) reds[j>>5] = s;
    __syncthreads();
    float sum = reds[0]+reds[1]+reds[2]+reds[3]+reds[4]+reds[5];
    g_attn[((size_t)b*CH + i)*CH + j] = e / sum;
}

// ---------------- out[b] = A2[b] @ X[b] + bp2 ----------------
__global__ __launch_bounds__(256) void final_gemm(const float* __restrict__ xin,
                                                  float* __restrict__ out) {
    __shared__ float As[16][68], Bs[16][68];
    int b = blockIdx.z;
    int m0 = blockIdx.x * 64;      // 3 tiles
    int n0 = blockIdx.y * 64;      // 256 tiles
    const float* Ab = g_A2 + (size_t)b*CH*CH;
    const float* Xb = xin + (size_t)b*CH*HW;
    int tid = threadIdx.x;
    int tx = tid & 15, ty = tid >> 4;
    int alr = tid >> 2, alk = (tid & 3)*4;
    int bkr = tid >> 4, bnq = (tid & 15)*4;
    float acc[4][4] = {};
    for (int k0 = 0; k0 < CH; k0 += 16) {
        float4 av = *(const float4*)&Ab[(m0+alr)*CH + k0 + alk];
        float4 bv = *(const float4*)&Xb[(size_t)(k0+bkr)*HW + n0 + bnq];
        __syncthreads();
        As[alk+0][alr]=av.x; As[alk+1][alr]=av.y; As[alk+2][alr]=av.z; As[alk+3][alr]=av.w;
        *(float4*)&Bs[bkr][bnq] = bv;
        __syncthreads();
        #pragma unroll
        for (int k = 0; k < 16; ++k) {
            float4 a4 = *(const float4*)&As[k][ty*4];
            float4 b4 = *(const float4*)&Bs[k][tx*4];
            float aa[4] = {a4.x,a4.y,a4.z,a4.w};
            float bb[4] = {b4.x,b4.y,b4.z,b4.w};
            #pragma unroll
            for (int ii = 0; ii < 4; ++ii)
                #pragma unroll
                for (int jj = 0; jj < 4; ++jj)
                    acc[ii][jj] += aa[ii]*bb[jj];
        }
    }
    #pragma unroll
    for (int ii = 0; ii < 4; ++ii) {
        int m = m0 + ty*4 + ii;
        float bias = g_bp2[m];
        float4 o = {acc[ii][0]+bias, acc[ii][1]+bias, acc[ii][2]+bias, acc[ii][3]+bias};
        *(float4*)&out[((size_t)b*CH + m)*HW + n0 + tx*4] = o;
    }
}

// ---------------- launch ----------------
extern "C" void kernel_launch(void* const* d_in, const int* in_sizes, int n_in,
                              void* d_out, int out_size) {
    const float* x_in   = (const float*)d_in[0];
    const float* w_split= (const float*)d_in[1];
    const float* w_q    = (const float*)d_in[2];
    const float* w_k    = (const float*)d_in[3];
    const float* w_v    = (const float*)d_in[4];
    const float* w_proj = (const float*)d_in[5];
    const float* b_proj = (const float*)d_in[6];
    const float* w_out  = (const float*)d_in[7];
    float* out = (float*)d_out;

    float *pWq, *pWk, *pWv, *pWp2, *pS, *pT1, *pT2, *pG, *pAttn, *pA1, *pA2;
    cudaGetSymbolAddress((void**)&pWq,  g_Wq);
    cudaGetSymbolAddress((void**)&pWk,  g_Wk);
    cudaGetSymbolAddress((void**)&pWv,  g_Wv);
    cudaGetSymbolAddress((void**)&pWp2, g_Wp2);
    cudaGetSymbolAddress((void**)&pS,   g_S);
    cudaGetSymbolAddress((void**)&pT1,  g_T1);
    cudaGetSymbolAddress((void**)&pT2,  g_T2);
    cudaGetSymbolAddress((void**)&pG,   g_G);
    cudaGetSymbolAddress((void**)&pAttn,g_attn);
    cudaGetSymbolAddress((void**)&pA1,  g_A1);
    cudaGetSymbolAddress((void**)&pA2,  g_A2);

    dim3 tb(16, 16);

    // combined channel maps (tiny)
    gemm192<<<dim3(144,1), tb>>>(w_q,  w_split, pWq,  0,0,0);
    gemm192<<<dim3(144,1), tb>>>(w_k,  w_split, pWk,  0,0,0);
    gemm192<<<dim3(144,1), tb>>>(w_v,  w_split, pWv,  0,0,0);
    gemm192<<<dim3(144,1), tb>>>(w_out,w_proj,  pWp2, 0,0,0);
    bias_combine<<<1, 192>>>(w_out, b_proj);

    // S = X X^T per batch (big GEMM #1)
    xxt_partial<<<dim3(3,3,NB*KSPLIT), 256>>>(x_in);
    s_reduce<<<(NB*CH*CH)/256, 256>>>();

    // Gram + norms in channel space
    gemm192<<<dim3(144,NB), tb>>>(pS,  pWq, pT1, 1,0,1);   // T1 = S Wq'^T
    gemm192<<<dim3(144,NB), tb>>>(pS,  pWk, pT2, 1,0,1);   // T2 = S Wk'^T
    diag_norms<<<dim3(NB,2), 192>>>();
    gemm192<<<dim3(144,NB), tb>>>(pWk, pT1, pG,  0,1,0);   // G = Wk' T1

    softmax_rows<<<dim3(CH,NB), 192>>>();

    gemm192<<<dim3(144,NB), tb>>>(pWp2, pAttn, pA1, 0,1,0); // A1 = Wp2 attn
    gemm192<<<dim3(144,NB), tb>>>(pA1,  pWv,   pA2, 1,0,0); // A2 = A1 Wv'

    // out = A2 X + bp2 (big GEMM #2)
    final_gemm<<<dim3(3,256,NB), 256>>>(x_in, out);
}

// round 3
// speedup vs baseline: 1.0019x; 1.0019x over previous
#include <cuda_runtime.h>

#define CH 192
#define NB 8
#define HW 16384
#define KSPLIT 8
#define KCHUNK (HW / KSPLIT)
#define EPSN 1e-12f

// ---------------- scratch (static device memory; no allocations) ----------------
__device__ float g_Wq[CH*CH], g_Wk[CH*CH], g_Wv[CH*CH], g_Wp2[CH*CH], g_bp2[CH];
__device__ float g_Spart[NB*KSPLIT*CH*CH];
__device__ float g_S[NB*CH*CH], g_T1[NB*CH*CH], g_T2[NB*CH*CH];
__device__ float g_G[NB*CH*CH], g_attn[NB*CH*CH], g_A1[NB*CH*CH], g_A2[NB*CH*CH];
__device__ float g_nk2[NB*CH], g_nq2[NB*CH];

// ---------------- generic tiny 192x192 GEMM: C[b] = A (x) B ----------------
// aBatched/bBatched: operand has per-batch stride CH*CH. transB: C = A * B^T.
__global__ void gemm192(const float* __restrict__ A, const float* __restrict__ Bm,
                        float* __restrict__ Cm, int aBatched, int bBatched, int transB) {
    __shared__ float As[16][17], Bs[16][17];
    int b = blockIdx.y;
    const float* Ab = A  + (aBatched ? b*CH*CH : 0);
    const float* Bb = Bm + (bBatched ? b*CH*CH : 0);
    float* Cb = Cm + b*CH*CH;
    int tile = blockIdx.x;           // 0..143 (12x12 tiles of 16)
    int i0 = (tile / 12) * 16;
    int j0 = (tile % 12) * 16;
    int tx = threadIdx.x, ty = threadIdx.y;
    float acc = 0.f;
    if (transB) {
        for (int kk = 0; kk < CH; kk += 16) {
            As[ty][tx] = Ab[(i0+ty)*CH + kk + tx];
            Bs[ty][tx] = Bb[(j0+ty)*CH + kk + tx];
            __syncthreads();
            #pragma unroll
            for (int k = 0; k < 16; ++k) acc += As[ty][k] * Bs[tx][k];
            __syncthreads();
        }
    } else {
        for (int kk = 0; kk < CH; kk += 16) {
            As[ty][tx] = Ab[(i0+ty)*CH + kk + tx];
            Bs[ty][tx] = Bb[(kk+ty)*CH + j0 + tx];
            __syncthreads();
            #pragma unroll
            for (int k = 0; k < 16; ++k) acc += As[ty][k] * Bs[k][tx];
            __syncthreads();
        }
    }
    Cb[(i0+ty)*CH + j0 + tx] = acc;
}

// bp2[f] = sum_o w_out[f][o] * b_proj[o]
__global__ void bias_combine(const float* __restrict__ w_out, const float* __restrict__ b_proj) {
    int f = threadIdx.x;
    if (f < CH) {
        float s = 0.f;
        for (int o = 0; o < CH; ++o) s += w_out[f*CH+o] * b_proj[o];
        g_bp2[f] = s;
    }
}

// ---------------- S = X X^T (per batch), split-K partials (deterministic) ----------------
__global__ __launch_bounds__(256) void xxt_partial(const float* __restrict__ xin) {
    __shared__ float As[16][68], Bs[16][68];
    int bz = blockIdx.z;
    int b = bz / KSPLIT, p = bz % KSPLIT;
    const float* Xb = xin + (size_t)b * CH * HW;
    int i0 = blockIdx.x * 64, j0 = blockIdx.y * 64;
    int tid = threadIdx.x;
    int tx = tid & 15, ty = tid >> 4;
    int lr = tid >> 2;             // 0..63
    int lk = (tid & 3) * 4;        // 0,4,8,12
    int kstart = p * KCHUNK;
    float acc[4][4] = {};
    for (int kt = 0; kt < KCHUNK; kt += 16) {
        int kb = kstart + kt;
        float4 av = *(const float4*)&Xb[(size_t)(i0+lr)*HW + kb + lk];
        float4 bv = *(const float4*)&Xb[(size_t)(j0+lr)*HW + kb + lk];
        __syncthreads();
        As[lk+0][lr]=av.x; As[lk+1][lr]=av.y; As[lk+2][lr]=av.z; As[lk+3][lr]=av.w;
        Bs[lk+0][lr]=bv.x; Bs[lk+1][lr]=bv.y; Bs[lk+2][lr]=bv.z; Bs[lk+3][lr]=bv.w;
        __syncthreads();
        #pragma unroll
        for (int k = 0; k < 16; ++k) {
            float4 a4 = *(const float4*)&As[k][ty*4];
            float4 b4 = *(const float4*)&Bs[k][tx*4];
            float aa[4] = {a4.x,a4.y,a4.z,a4.w};
            float bb[4] = {b4.x,b4.y,b4.z,b4.w};
            #pragma unroll
            for (int ii = 0; ii < 4; ++ii)
                #pragma unroll
                for (int jj = 0; jj < 4; ++jj)
                    acc[ii][jj] += aa[ii]*bb[jj];
        }
    }
    float* outp = g_Spart + (size_t)(b*KSPLIT + p)*CH*CH;
    #pragma unroll
    for (int ii = 0; ii < 4; ++ii) {
        float4 o = {acc[ii][0], acc[ii][1], acc[ii][2], acc[ii][3]};
        *(float4*)&outp[(i0+ty*4+ii)*CH + j0 + tx*4] = o;
    }
}

__global__ void s_reduce() {
    int idx = blockIdx.x*256 + threadIdx.x;   // over NB*CH*CH = 294912
    if (idx < NB*CH*CH) {
        int b = idx / (CH*CH), e = idx % (CH*CH);
        float s = 0.f;
        #pragma unroll
        for (int p = 0; p < KSPLIT; ++p)
            s += g_Spart[(size_t)(b*KSPLIT+p)*CH*CH + e];
        g_S[idx] = s;
    }
}

// nq2[b][j] = diag(Wq' T1)_j ; nk2[b][i] = diag(Wk' T2)_i
__global__ void diag_norms() {
    int b = blockIdx.x, which = blockIdx.y;
    int j = threadIdx.x;
    if (j >= CH) return;
    const float* W = which ? g_Wk : g_Wq;
    const float* T = (which ? g_T2 : g_T1) + (size_t)b*CH*CH;
    float s = 0.f;
    for (int m = 0; m < CH; ++m) s += W[j*CH+m] * T[m*CH+j];
    (which ? g_nk2 : g_nq2)[b*CH+j] = s;
}

// attn[i][j] = softmax_j( G[i][j] / (max(||k_i||,eps)*max(||q_j||,eps)) )
__global__ void softmax_rows() {
    int b = blockIdx.y, i = blockIdx.x;
    int j = threadIdx.x;                  // 192 threads, 6 full warps
    const float* Grow = g_G + ((size_t)b*CH + i)*CH;
    float dk = fmaxf(sqrtf(g_nk2[b*CH+i]), EPSN);
    float dq = fmaxf(sqrtf(g_nq2[b*CH+j]), EPSN);
    float L = Grow[j] / (dk*dq);
    __shared__ float redm[6], reds[6];
    float m = L;
    #pragma unroll
    for (int o = 16; o > 0; o >>= 1) m = fmaxf(m, __shfl_xor_sync(0xffffffffu, m, o));
    if ((j & 31) == 0) redm[j>>5] = m;
    __syncthreads();
    float mx = fmaxf(fmaxf(fmaxf(redm[0],redm[1]),fmaxf(redm[2],redm[3])),fmaxf(redm[4],redm[5]));
    float e = expf(L - mx);
    float s = e;
    #pragma unroll
    for (int o = 16; o > 0; o >>= 1) s += __shfl_xor_sync(0xffffffffu, s, o);
    if ((j & 31) == 0) reds[j>>5] = s;
    __syncthreads();
    float sum = reds[0]+reds[1]+reds[2]+reds[3]+reds[4]+reds[5];
    g_attn[((size_t)b*CH + i)*CH + j] = e / sum;
}

// ---------------- out[b] = A2[b] @ X[b] + bp2 ----------------
__global__ __launch_bounds__(256) void final_gemm(const float* __restrict__ xin,
                                                  float* __restrict__ out) {
    __shared__ float As[16][68], Bs[16][68];
    int b = blockIdx.z;
    int m0 = blockIdx.x * 64;      // 3 tiles
    int n0 = blockIdx.y * 64;      // 256 tiles
    const float* Ab = g_A2 + (size_t)b*CH*CH;
    const float* Xb = xin + (size_t)b*CH*HW;
    int tid = threadIdx.x;
    int tx = tid & 15, ty = tid >> 4;
    int alr = tid >> 2, alk = (tid & 3)*4;
    int bkr = tid >> 4, bnq = (tid & 15)*4;
    float acc[4][4] = {};
    for (int k0 = 0; k0 < CH; k0 += 16) {
        float4 av = *(const float4*)&Ab[(m0+alr)*CH + k0 + alk];
        float4 bv = *(const float4*)&Xb[(size_t)(k0+bkr)*HW + n0 + bnq];
        __syncthreads();
        As[alk+0][alr]=av.x; As[alk+1][alr]=av.y; As[alk+2][alr]=av.z; As[alk+3][alr]=av.w;
        *(float4*)&Bs[bkr][bnq] = bv;
        __syncthreads();
        #pragma unroll
        for (int k = 0; k < 16; ++k) {
            float4 a4 = *(const float4*)&As[k][ty*4];
            float4 b4 = *(const float4*)&Bs[k][tx*4];
            float aa[4] = {a4.x,a4.y,a4.z,a4.w};
            float bb[4] = {b4.x,b4.y,b4.z,b4.w};
            #pragma unroll
            for (int ii = 0; ii < 4; ++ii)
                #pragma unroll
                for (int jj = 0; jj < 4; ++jj)
                    acc[ii][jj] += aa[ii]*bb[jj];
        }
    }
    #pragma unroll
    for (int ii = 0; ii < 4; ++ii) {
        int m = m0 + ty*4 + ii;
        float bias = g_bp2[m];
        float4 o = {acc[ii][0]+bias, acc[ii][1]+bias, acc[ii][2]+bias, acc[ii][3]+bias};
        *(float4*)&out[((size_t)b*CH + m)*HW + n0 + tx*4] = o;
    }
}

// ---------------- launch ----------------
extern "C" void kernel_launch(void* const* d_in, const int* in_sizes, int n_in,
                              void* d_out, int out_size) {
    const float* x_in   = (const float*)d_in[0];
    const float* w_split= (const float*)d_in[1];
    const float* w_q    = (const float*)d_in[2];
    const float* w_k    = (const float*)d_in[3];
    const float* w_v    = (const float*)d_in[4];
    const float* w_proj = (const float*)d_in[5];
    const float* b_proj = (const float*)d_in[6];
    const float* w_out  = (const float*)d_in[7];
    float* out = (float*)d_out;

    float *pWq, *pWk, *pWv, *pWp2, *pS, *pT1, *pT2, *pG, *pAttn, *pA1, *pA2;
    cudaGetSymbolAddress((void**)&pWq,  g_Wq);
    cudaGetSymbolAddress((void**)&pWk,  g_Wk);
    cudaGetSymbolAddress((void**)&pWv,  g_Wv);
    cudaGetSymbolAddress((void**)&pWp2, g_Wp2);
    cudaGetSymbolAddress((void**)&pS,   g_S);
    cudaGetSymbolAddress((void**)&pT1,  g_T1);
    cudaGetSymbolAddress((void**)&pT2,  g_T2);
    cudaGetSymbolAddress((void**)&pG,   g_G);
    cudaGetSymbolAddress((void**)&pAttn,g_attn);
    cudaGetSymbolAddress((void**)&pA1,  g_A1);
    cudaGetSymbolAddress((void**)&pA2,  g_A2);

    dim3 tb(16, 16);

    // combined channel maps (tiny)
    gemm192<<<dim3(144,1), tb>>>(w_q,  w_split, pWq,  0,0,0);
    gemm192<<<dim3(144,1), tb>>>(w_k,  w_split, pWk,  0,0,0);
    gemm192<<<dim3(144,1), tb>>>(w_v,  w_split, pWv,  0,0,0);
    gemm192<<<dim3(144,1), tb>>>(w_out,w_proj,  pWp2, 0,0,0);
    bias_combine<<<1, 192>>>(w_out, b_proj);

    // S = X X^T per batch (big GEMM #1)
    xxt_partial<<<dim3(3,3,NB*KSPLIT), 256>>>(x_in);
    s_reduce<<<(NB*CH*CH)/256, 256>>>();

    // Gram + norms in channel space
    gemm192<<<dim3(144,NB), tb>>>(pS,  pWq, pT1, 1,0,1);   // T1 = S Wq'^T
    gemm192<<<dim3(144,NB), tb>>>(pS,  pWk, pT2, 1,0,1);   // T2 = S Wk'^T
    diag_norms<<<dim3(NB,2), 192>>>();
    gemm192<<<dim3(144,NB), tb>>>(pWk, pT1, pG,  0,1,0);   // G = Wk' T1

    softmax_rows<<<dim3(CH,NB), 192>>>();

    gemm192<<<dim3(144,NB), tb>>>(pWp2, pAttn, pA1, 0,1,0); // A1 = Wp2 attn
    gemm192<<<dim3(144,NB), tb>>>(pA1,  pWv,   pA2, 1,0,0); // A2 = A1 Wv'

    // out = A2 X + bp2 (big GEMM #2)
    final_gemm<<<dim3(3,256,NB), 256>>>(x_in, out);
}